// round 15
// baseline (speedup 1.0000x reference)
#include <cuda_runtime.h>
#include <cstdint>

#define MAXN 100000
#define MAXE 1600000

// ---------------- static device scratch (allocation-free rule) ----------------
// Single large buffer (102.4MB): holds A1 = Agg(x) [N x 128] first, then A2 = Agg(H) [N x 256].
__device__ float4 g_S[(size_t)MAXN * 64];
__device__ int    g_cnt[MAXN];
__device__ int    g_rowptr[MAXN];
__device__ int    g_cursor[MAXN];
__device__ int    g_excl[MAXN];
__device__ int    g_bsums[1024];
__device__ float  g_dinv[MAXN];
__device__ int    g_col[MAXE];

// ---------------- CSR build ----------------
__global__ void zero_cnt_kernel(int n) {
    int i = blockIdx.x * blockDim.x + threadIdx.x;
    if (i < n) g_cnt[i] = 0;
}

// edge_index is int32 [2, E]: row 0 = src, row 1 = dst. All indices bounds-checked.
__global__ void count_kernel(const int* __restrict__ ei, int e, int n) {
    int i = blockIdx.x * blockDim.x + threadIdx.x;
    if (i < e) {
        int dst = ei[e + i];
        if ((unsigned)dst < (unsigned)n) atomicAdd(&g_cnt[dst], 1);
    }
}

__global__ void scan_block_kernel(int n) {
    __shared__ int sh[1024];
    int i = blockIdx.x * 1024 + threadIdx.x;
    int v = (i < n) ? g_cnt[i] : 0;
    sh[threadIdx.x] = v;
    __syncthreads();
    for (int off = 1; off < 1024; off <<= 1) {
        int t = (threadIdx.x >= off) ? sh[threadIdx.x - off] : 0;
        __syncthreads();
        sh[threadIdx.x] += t;
        __syncthreads();
    }
    if (i < n) g_excl[i] = sh[threadIdx.x] - v;   // exclusive within block
    if (threadIdx.x == 1023) g_bsums[blockIdx.x] = sh[1023];
}

__global__ void scan_partials_kernel(int nb) {
    if (threadIdx.x == 0 && blockIdx.x == 0) {
        int acc = 0;
        for (int i = 0; i < nb; i++) { int t = g_bsums[i]; g_bsums[i] = acc; acc += t; }
    }
}

__global__ void scan_add_kernel(int n) {
    int i = blockIdx.x * blockDim.x + threadIdx.x;
    if (i < n) {
        int v = g_excl[i] + g_bsums[i >> 10];
        g_rowptr[i] = v;
        g_cursor[i] = v;
        g_dinv[i] = rsqrtf((float)(g_cnt[i] + 1));   // deg incl. self-loop
    }
}

__global__ void fill_kernel(const int* __restrict__ ei, int e, int n) {
    int i = blockIdx.x * blockDim.x + threadIdx.x;
    if (i < e) {
        int src = ei[i];
        int dst = ei[e + i];
        if ((unsigned)src < (unsigned)n && (unsigned)dst < (unsigned)n) {
            int pos = atomicAdd(&g_cursor[dst], 1);
            if ((unsigned)pos < (unsigned)MAXE) g_col[pos] = src;
        }
    }
}

// ---------------- agg over x (128 feats): A1 = D^-1/2 (A+I) D^-1/2 x -> g_S (stride 32 f4) ----
__global__ __launch_bounds__(256) void agg_x_kernel(const float* __restrict__ x, int n) {
    int gw = (blockIdx.x * blockDim.x + threadIdx.x) >> 5;
    if (gw >= n) return;
    int lane = threadIdx.x & 31;
    const float4* xf = (const float4*)x;       // 32 float4 per row
    int base = g_rowptr[gw];
    int deg  = g_cnt[gw];
    float ax = 0.f, ay = 0.f, az = 0.f, aw = 0.f;
    for (int k = 0; k < deg; k++) {
        int   s = g_col[base + k];
        float w = g_dinv[s];
        float4 v = xf[(size_t)s * 32 + lane];
        ax += w * v.x; ay += w * v.y; az += w * v.z; aw += w * v.w;
    }
    float di = g_dinv[gw];
    float4 sv = xf[(size_t)gw * 32 + lane];
    ax = di * (ax + di * sv.x); ay = di * (ay + di * sv.y);
    az = di * (az + di * sv.z); aw = di * (aw + di * sv.w);
    g_S[(size_t)gw * 32 + lane] = make_float4(ax, ay, az, aw);
}

// ---------------- agg over H (256 feats): A2 = Norm-agg(H) -> g_S (stride 64 f4) --------------
__global__ __launch_bounds__(256) void agg_h_kernel(const float* __restrict__ H, int n) {
    int gw = (blockIdx.x * blockDim.x + threadIdx.x) >> 5;
    if (gw >= n) return;
    int lane = threadIdx.x & 31;
    const float4* hf = (const float4*)H;       // 64 float4 per row
    int base = g_rowptr[gw];
    int deg  = g_cnt[gw];
    float a0x = 0.f, a0y = 0.f, a0z = 0.f, a0w = 0.f;
    float a1x = 0.f, a1y = 0.f, a1z = 0.f, a1w = 0.f;
    for (int k = 0; k < deg; k++) {
        int   s = g_col[base + k];
        float w = g_dinv[s];
        float4 v0 = hf[(size_t)s * 64 + lane];
        float4 v1 = hf[(size_t)s * 64 + lane + 32];
        a0x += w * v0.x; a0y += w * v0.y; a0z += w * v0.z; a0w += w * v0.w;
        a1x += w * v1.x; a1y += w * v1.y; a1z += w * v1.z; a1w += w * v1.w;
    }
    float di = g_dinv[gw];
    float4 s0 = hf[(size_t)gw * 64 + lane];
    float4 s1 = hf[(size_t)gw * 64 + lane + 32];
    a0x = di * (a0x + di * s0.x); a0y = di * (a0y + di * s0.y);
    a0z = di * (a0z + di * s0.z); a0w = di * (a0w + di * s0.w);
    a1x = di * (a1x + di * s1.x); a1y = di * (a1y + di * s1.y);
    a1z = di * (a1z + di * s1.z); a1w = di * (a1w + di * s1.w);
    g_S[(size_t)gw * 64 + lane]      = make_float4(a0x, a0y, a0z, a0w);
    g_S[(size_t)gw * 64 + lane + 32] = make_float4(a1x, a1y, a1z, a1w);
}

// ---------------- GEMM 1: H = relu(A1 @ W1 + b1) -> C (d_out).  A1 = g_S, K=128, Nc=256 ------
__global__ __launch_bounds__(256) void gemm1_kernel(
    const float* __restrict__ B, const float* __restrict__ bias,
    float* __restrict__ C, int M)
{
    const int K = 128, Nc = 256;
    const float* A = (const float*)g_S;
    __shared__ float As[8][128];
    __shared__ float Bs[8][128];
    int tid  = threadIdx.x;
    int brow = blockIdx.y * 128;
    int bcol = blockIdx.x * 128;
    int ty = tid >> 4, tx = tid & 15;
    float acc[8][8];
#pragma unroll
    for (int i = 0; i < 8; i++)
#pragma unroll
        for (int j = 0; j < 8; j++) acc[i][j] = 0.f;

    int arow = tid >> 1, ak = (tid & 1) * 4;
    int bk = tid >> 5,  bc = (tid & 31) * 4;

    for (int k0 = 0; k0 < K; k0 += 8) {
        float4 av = make_float4(0.f, 0.f, 0.f, 0.f);
        int gr = brow + arow;
        if (gr < M) av = *(const float4*)(A + (size_t)gr * K + k0 + ak);
        As[ak + 0][arow] = av.x; As[ak + 1][arow] = av.y;
        As[ak + 2][arow] = av.z; As[ak + 3][arow] = av.w;
        *(float4*)&Bs[bk][bc] = *(const float4*)(B + (size_t)(k0 + bk) * Nc + bcol + bc);
        __syncthreads();
#pragma unroll
        for (int kk = 0; kk < 8; kk++) {
            float a[8], b[8];
#pragma unroll
            for (int i = 0; i < 8; i++) a[i] = As[kk][ty * 8 + i];
#pragma unroll
            for (int j = 0; j < 8; j++) b[j] = Bs[kk][tx * 8 + j];
#pragma unroll
            for (int i = 0; i < 8; i++)
#pragma unroll
                for (int j = 0; j < 8; j++) acc[i][j] += a[i] * b[j];
        }
        __syncthreads();
    }
    float bv[8];
#pragma unroll
    for (int j = 0; j < 8; j++) bv[j] = bias[bcol + tx * 8 + j];
#pragma unroll
    for (int i = 0; i < 8; i++) {
        int gr = brow + ty * 8 + i;
        if (gr < M) {
            float4* cp = (float4*)(C + (size_t)gr * Nc + bcol + tx * 8);
            cp[0] = make_float4(fmaxf(acc[i][0] + bv[0], 0.f), fmaxf(acc[i][1] + bv[1], 0.f),
                                fmaxf(acc[i][2] + bv[2], 0.f), fmaxf(acc[i][3] + bv[3], 0.f));
            cp[1] = make_float4(fmaxf(acc[i][4] + bv[4], 0.f), fmaxf(acc[i][5] + bv[5], 0.f),
                                fmaxf(acc[i][6] + bv[6], 0.f), fmaxf(acc[i][7] + bv[7], 0.f));
        }
    }
}

// ---------------- GEMM 2 (fused final): C = relu(A2@W2 + x@Wp + b2 + bp) ---------------------
// Phase 0: A = g_S (K=256) with B=W2.  Phase 1: A = x (K=128) with B=Wp.  Then bias+relu.
__global__ __launch_bounds__(256) void gemm2_kernel(
    const float* __restrict__ x, const float* __restrict__ W2,
    const float* __restrict__ Wp, const float* __restrict__ b2,
    const float* __restrict__ bp, float* __restrict__ C, int M)
{
    const int Nc = 256;
    __shared__ float As[8][128];
    __shared__ float Bs[8][128];
    int tid  = threadIdx.x;
    int brow = blockIdx.y * 128;
    int bcol = blockIdx.x * 128;
    int ty = tid >> 4, tx = tid & 15;
    float acc[8][8];
#pragma unroll
    for (int i = 0; i < 8; i++)
#pragma unroll
        for (int j = 0; j < 8; j++) acc[i][j] = 0.f;

    int arow = tid >> 1, ak = (tid & 1) * 4;
    int bk = tid >> 5,  bc = (tid & 31) * 4;

    for (int phase = 0; phase < 2; phase++) {
        const float* A  = (phase == 0) ? (const float*)g_S : x;
        const float* B  = (phase == 0) ? W2 : Wp;
        const int    K  = (phase == 0) ? 256 : 128;
        for (int k0 = 0; k0 < K; k0 += 8) {
            float4 av = make_float4(0.f, 0.f, 0.f, 0.f);
            int gr = brow + arow;
            if (gr < M) av = *(const float4*)(A + (size_t)gr * K + k0 + ak);
            As[ak + 0][arow] = av.x; As[ak + 1][arow] = av.y;
            As[ak + 2][arow] = av.z; As[ak + 3][arow] = av.w;
            *(float4*)&Bs[bk][bc] = *(const float4*)(B + (size_t)(k0 + bk) * Nc + bcol + bc);
            __syncthreads();
#pragma unroll
            for (int kk = 0; kk < 8; kk++) {
                float a[8], b[8];
#pragma unroll
                for (int i = 0; i < 8; i++) a[i] = As[kk][ty * 8 + i];
#pragma unroll
                for (int j = 0; j < 8; j++) b[j] = Bs[kk][tx * 8 + j];
#pragma unroll
                for (int i = 0; i < 8; i++)
#pragma unroll
                    for (int j = 0; j < 8; j++) acc[i][j] += a[i] * b[j];
            }
            __syncthreads();
        }
    }
    float bv[8];
#pragma unroll
    for (int j = 0; j < 8; j++) {
        int col = bcol + tx * 8 + j;
        bv[j] = b2[col] + bp[col];
    }
#pragma unroll
    for (int i = 0; i < 8; i++) {
        int gr = brow + ty * 8 + i;
        if (gr < M) {
            float4* cp = (float4*)(C + (size_t)gr * Nc + bcol + tx * 8);
            cp[0] = make_float4(fmaxf(acc[i][0] + bv[0], 0.f), fmaxf(acc[i][1] + bv[1], 0.f),
                                fmaxf(acc[i][2] + bv[2], 0.f), fmaxf(acc[i][3] + bv[3], 0.f));
            cp[1] = make_float4(fmaxf(acc[i][4] + bv[4], 0.f), fmaxf(acc[i][5] + bv[5], 0.f),
                                fmaxf(acc[i][6] + bv[6], 0.f), fmaxf(acc[i][7] + bv[7], 0.f));
        }
    }
}

// ---------------- host launch: kernel launches ONLY ----------------
extern "C" void kernel_launch(void* const* d_in, const int* in_sizes, int n_in,
                              void* d_out, int out_size)
{
    // ---- size-based input binding (robust to metadata ordering) ----
    // x: N*128 = 12,800,000   ei: 2*E = 3,200,000   W2: 65,536
    // W1/Wp: 32,768 each (relative order preserved: W1 first in both dict and
    // alphabetical order)   b1/b2/bp: 256 each (relative order b1,b2,bp in both)
    const float* x  = nullptr;  const int* ei = nullptr;
    const float* W1 = nullptr;  const float* W2 = nullptr; const float* Wp = nullptr;
    const float* b1 = nullptr;  const float* b2 = nullptr; const float* bp = nullptr;
    {
        int nw = 0, nb = 0;
        const float* wbig[2] = {nullptr, nullptr};
        const float* bias[3] = {nullptr, nullptr, nullptr};
        const float* xcand = nullptr; const int* eicand = nullptr;
        const float* w2cand = nullptr;
        for (int i = 0; i < n_in; i++) {
            int sz = in_sizes[i];
            if (sz >= 4000000)                      xcand  = (const float*)d_in[i];
            else if (sz >= 1000000)                 eicand = (const int*)d_in[i];
            else if (sz == 65536)                   w2cand = (const float*)d_in[i];
            else if (sz == 32768 && nw < 2)         wbig[nw++] = (const float*)d_in[i];
            else if (sz == 256 && nb < 3)           bias[nb++] = (const float*)d_in[i];
        }
        x = xcand; ei = eicand; W2 = w2cand;
        W1 = wbig[0]; Wp = wbig[1];
        b1 = bias[0]; b2 = bias[1]; bp = bias[2];
        if (!x || !ei || !W1 || !W2 || !Wp || !b1 || !b2 || !bp) {
            // fallback: positional (reference dict order)
            x  = (const float*)d_in[0]; ei = (const int*)d_in[1];
            W1 = (const float*)d_in[2]; b1 = (const float*)d_in[3];
            W2 = (const float*)d_in[4]; b2 = (const float*)d_in[5];
            Wp = (const float*)d_in[6]; bp = (const float*)d_in[7];
        }
    }
    float* out = (float*)d_out;

    int N_ = out_size / 256;                 if (N_ > MAXN) N_ = MAXN;
    int E_ = 0;
    for (int i = 0; i < n_in; i++)
        if ((const int*)d_in[i] == ei) { E_ = in_sizes[i] / 2; break; }
    if (E_ > MAXE) E_ = MAXE;

    int tb = 256;
    int nbN = (N_ + tb - 1) / tb;
    int nbE = (E_ + tb - 1) / tb;
    int nScan = (N_ + 1023) / 1024;

    // CSR build (edge_index as int32, all indices bounds-guarded)
    zero_cnt_kernel<<<nbN, tb>>>(N_);
    count_kernel<<<nbE, tb>>>(ei, E_, N_);
    scan_block_kernel<<<nScan, 1024>>>(N_);
    scan_partials_kernel<<<1, 32>>>(nScan);
    scan_add_kernel<<<nbN, tb>>>(N_);
    fill_kernel<<<nbE, tb>>>(ei, E_, N_);

    int aggBlocks = (N_ * 32 + tb - 1) / tb;
    dim3 gGrid(2, (N_ + 127) / 128);   // 256 cols / 128

    // A1 = Agg(x) -> g_S
    agg_x_kernel<<<aggBlocks, tb>>>(x, N_);
    // H = relu(A1 @ W1 + b1) -> d_out (scratch)
    gemm1_kernel<<<gGrid, tb>>>(W1, b1, out, N_);
    // A2 = Agg(H) -> g_S
    agg_h_kernel<<<aggBlocks, tb>>>(out, N_);
    // out = relu(A2 @ W2 + x @ Wp + b2 + bp)
    gemm2_kernel<<<gGrid, tb>>>(x, W2, Wp, b2, bp, out, N_);
}

// round 16
// speedup vs baseline: 1.8284x; 1.8284x over previous
#include <cuda_runtime.h>
#include <cstdint>

#define MAXN 100000
#define MAXE 1600000

// ---------------- static device scratch (allocation-free rule) ----------------
// Single large buffer (102.4MB): holds A1 = Agg(x) [N x 128] first, then A2 = Agg(H) [N x 256].
__device__ float4 g_S[(size_t)MAXN * 64];
__device__ int    g_cnt[MAXN];
__device__ int    g_rowptr[MAXN];
__device__ int    g_cursor[MAXN];
__device__ int    g_excl[MAXN];
__device__ int    g_bsums[1024];
__device__ float  g_dinv[MAXN];
__device__ int    g_col[MAXE];

// ---------------- CSR build ----------------
__global__ void zero_cnt_kernel(int n) {
    int i = blockIdx.x * blockDim.x + threadIdx.x;
    if (i < n) g_cnt[i] = 0;
}

// edge_index is int32 [2, E]: row 0 = src, row 1 = dst. All indices bounds-checked.
__global__ void count_kernel(const int* __restrict__ ei, int e, int n) {
    int i = blockIdx.x * blockDim.x + threadIdx.x;
    if (i < e) {
        int dst = ei[e + i];
        if ((unsigned)dst < (unsigned)n) atomicAdd(&g_cnt[dst], 1);
    }
}

__global__ void scan_block_kernel(int n) {
    __shared__ int sh[1024];
    int i = blockIdx.x * 1024 + threadIdx.x;
    int v = (i < n) ? g_cnt[i] : 0;
    sh[threadIdx.x] = v;
    __syncthreads();
    for (int off = 1; off < 1024; off <<= 1) {
        int t = (threadIdx.x >= off) ? sh[threadIdx.x - off] : 0;
        __syncthreads();
        sh[threadIdx.x] += t;
        __syncthreads();
    }
    if (i < n) g_excl[i] = sh[threadIdx.x] - v;   // exclusive within block
    if (threadIdx.x == 1023) g_bsums[blockIdx.x] = sh[1023];
}

__global__ void scan_partials_kernel(int nb) {
    if (threadIdx.x == 0 && blockIdx.x == 0) {
        int acc = 0;
        for (int i = 0; i < nb; i++) { int t = g_bsums[i]; g_bsums[i] = acc; acc += t; }
    }
}

__global__ void scan_add_kernel(int n) {
    int i = blockIdx.x * blockDim.x + threadIdx.x;
    if (i < n) {
        int v = g_excl[i] + g_bsums[i >> 10];
        g_rowptr[i] = v;
        g_cursor[i] = v;
        g_dinv[i] = rsqrtf((float)(g_cnt[i] + 1));   // deg incl. self-loop
    }
}

__global__ void fill_kernel(const int* __restrict__ ei, int e, int n) {
    int i = blockIdx.x * blockDim.x + threadIdx.x;
    if (i < e) {
        int src = ei[i];
        int dst = ei[e + i];
        if ((unsigned)src < (unsigned)n && (unsigned)dst < (unsigned)n) {
            int pos = atomicAdd(&g_cursor[dst], 1);
            if ((unsigned)pos < (unsigned)MAXE) g_col[pos] = src;
        }
    }
}

// ---------------- agg over x (128 feats): A1 = D^-1/2 (A+I) D^-1/2 x -> g_S (stride 32 f4) ----
__global__ __launch_bounds__(256) void agg_x_kernel(const float* __restrict__ x, int n) {
    int gw = (blockIdx.x * blockDim.x + threadIdx.x) >> 5;
    if (gw >= n) return;
    int lane = threadIdx.x & 31;
    const float4* xf = (const float4*)x;       // 32 float4 per row
    int base = g_rowptr[gw];
    int deg  = g_cnt[gw];
    float ax = 0.f, ay = 0.f, az = 0.f, aw = 0.f;
    for (int k = 0; k < deg; k++) {
        int   s = g_col[base + k];
        float w = g_dinv[s];
        float4 v = xf[(size_t)s * 32 + lane];
        ax += w * v.x; ay += w * v.y; az += w * v.z; aw += w * v.w;
    }
    float di = g_dinv[gw];
    float4 sv = xf[(size_t)gw * 32 + lane];
    ax = di * (ax + di * sv.x); ay = di * (ay + di * sv.y);
    az = di * (az + di * sv.z); aw = di * (aw + di * sv.w);
    g_S[(size_t)gw * 32 + lane] = make_float4(ax, ay, az, aw);
}

// ---------------- agg over H (256 feats): A2 = Norm-agg(H) -> g_S (stride 64 f4) --------------
__global__ __launch_bounds__(256) void agg_h_kernel(const float* __restrict__ H, int n) {
    int gw = (blockIdx.x * blockDim.x + threadIdx.x) >> 5;
    if (gw >= n) return;
    int lane = threadIdx.x & 31;
    const float4* hf = (const float4*)H;       // 64 float4 per row
    int base = g_rowptr[gw];
    int deg  = g_cnt[gw];
    float a0x = 0.f, a0y = 0.f, a0z = 0.f, a0w = 0.f;
    float a1x = 0.f, a1y = 0.f, a1z = 0.f, a1w = 0.f;
    for (int k = 0; k < deg; k++) {
        int   s = g_col[base + k];
        float w = g_dinv[s];
        float4 v0 = hf[(size_t)s * 64 + lane];
        float4 v1 = hf[(size_t)s * 64 + lane + 32];
        a0x += w * v0.x; a0y += w * v0.y; a0z += w * v0.z; a0w += w * v0.w;
        a1x += w * v1.x; a1y += w * v1.y; a1z += w * v1.z; a1w += w * v1.w;
    }
    float di = g_dinv[gw];
    float4 s0 = hf[(size_t)gw * 64 + lane];
    float4 s1 = hf[(size_t)gw * 64 + lane + 32];
    a0x = di * (a0x + di * s0.x); a0y = di * (a0y + di * s0.y);
    a0z = di * (a0z + di * s0.z); a0w = di * (a0w + di * s0.w);
    a1x = di * (a1x + di * s1.x); a1y = di * (a1y + di * s1.y);
    a1z = di * (a1z + di * s1.z); a1w = di * (a1w + di * s1.w);
    g_S[(size_t)gw * 64 + lane]      = make_float4(a0x, a0y, a0z, a0w);
    g_S[(size_t)gw * 64 + lane + 32] = make_float4(a1x, a1y, a1z, a1w);
}

// ---------------- tf32 tensor-core GEMM -------------------------------------------------------
// C[M,256] = relu( g_S @ B0 (K0)  [+ A1 @ B1 (K1)]  + bias_a [+ bias_b] )
// Block 128x128, 8 warps (2 M x 4 N), warp tile 64x32, mma.sync m16n8k8 tf32, fp32 accumulate.
// Smem layouts chosen conflict-free for fragment access:
//   As[m][k]   pad to 20  -> lane bank = (20g + tig) % 32  : permutation of 0..31
//   Bs[k][n]   pad to 136 -> lane bank = (8 tig + g) % 32  : permutation of 0..31

__device__ __forceinline__ uint32_t f2tf32(float f) {
    uint32_t u;
    asm("cvt.rna.tf32.f32 %0, %1;" : "=r"(u) : "f"(f));
    return u;
}

__device__ __forceinline__ void mma_tf32(float* c, const uint32_t* a, const uint32_t* b) {
    asm volatile(
        "mma.sync.aligned.m16n8k8.row.col.f32.tf32.tf32.f32 "
        "{%0,%1,%2,%3}, {%4,%5,%6,%7}, {%8,%9}, {%0,%1,%2,%3};"
        : "+f"(c[0]), "+f"(c[1]), "+f"(c[2]), "+f"(c[3])
        : "r"(a[0]), "r"(a[1]), "r"(a[2]), "r"(a[3]), "r"(b[0]), "r"(b[1]));
}

__global__ __launch_bounds__(256) void gemm_tf32_kernel(
    const float* __restrict__ B0, int K0,
    const float* __restrict__ A1, const float* __restrict__ B1, int K1,
    const float* __restrict__ bias_a, const float* __restrict__ bias_b,
    float* __restrict__ C, int M)
{
    const int Nc = 256;
    __shared__ float As[128][20];
    __shared__ float Bs[16][136];

    int tid  = threadIdx.x;
    int lane = tid & 31;
    int warp = tid >> 5;
    int g    = lane >> 2;          // 0..7
    int tig  = lane & 3;           // 0..3
    int wm   = warp & 1, wn = warp >> 1;     // 2 x 4 warp grid
    int WR   = wm * 64, WC = wn * 32;
    int brow = blockIdx.y * 128, bcol = blockIdx.x * 128;

    float acc[4][4][4];
#pragma unroll
    for (int mi = 0; mi < 4; mi++)
#pragma unroll
        for (int nj = 0; nj < 4; nj++)
#pragma unroll
            for (int r = 0; r < 4; r++) acc[mi][nj][r] = 0.f;

    for (int phase = 0; phase < 2; phase++) {
        const float* A = (phase == 0) ? (const float*)g_S : A1;
        const float* B = (phase == 0) ? B0 : B1;
        int K          = (phase == 0) ? K0 : K1;
        if (A == nullptr) break;

        for (int k0 = 0; k0 < K; k0 += 16) {
            // stage A: 128 rows x 16 k  (2 float4 per thread, vectorized both sides)
#pragma unroll
            for (int r = 0; r < 2; r++) {
                int f4  = tid + r * 256;
                int row = f4 >> 2;
                int kq  = (f4 & 3) * 4;
                float4 v = make_float4(0.f, 0.f, 0.f, 0.f);
                int grow = brow + row;
                if (grow < M) v = *(const float4*)(A + (size_t)grow * K + k0 + kq);
                *(float4*)&As[row][kq] = v;
            }
            // stage B: 16 k-rows x 128 cols
#pragma unroll
            for (int r = 0; r < 2; r++) {
                int f4 = tid + r * 256;
                int kr = f4 >> 5;
                int cc = (f4 & 31) * 4;
                *(float4*)&Bs[kr][cc] = *(const float4*)(B + (size_t)(k0 + kr) * Nc + bcol + cc);
            }
            __syncthreads();

#pragma unroll
            for (int kk = 0; kk < 16; kk += 8) {
                uint32_t af[4][4];
#pragma unroll
                for (int mi = 0; mi < 4; mi++) {
                    int r0 = WR + mi * 16 + g;
                    af[mi][0] = f2tf32(As[r0    ][kk + tig]);
                    af[mi][1] = f2tf32(As[r0 + 8][kk + tig]);
                    af[mi][2] = f2tf32(As[r0    ][kk + tig + 4]);
                    af[mi][3] = f2tf32(As[r0 + 8][kk + tig + 4]);
                }
                uint32_t bf[4][2];
#pragma unroll
                for (int nj = 0; nj < 4; nj++) {
                    bf[nj][0] = f2tf32(Bs[kk + tig    ][WC + nj * 8 + g]);
                    bf[nj][1] = f2tf32(Bs[kk + tig + 4][WC + nj * 8 + g]);
                }
#pragma unroll
                for (int mi = 0; mi < 4; mi++)
#pragma unroll
                    for (int nj = 0; nj < 4; nj++)
                        mma_tf32(acc[mi][nj], af[mi], bf[nj]);
            }
            __syncthreads();
        }
    }

    // epilogue: bias (+ optional second bias) + relu, float2 stores
#pragma unroll
    for (int mi = 0; mi < 4; mi++) {
        int r0 = brow + WR + mi * 16 + g;
#pragma unroll
        for (int nj = 0; nj < 4; nj++) {
            int col = bcol + WC + nj * 8 + tig * 2;
            float bv0 = bias_a[col];
            float bv1 = bias_a[col + 1];
            if (bias_b) { bv0 += bias_b[col]; bv1 += bias_b[col + 1]; }
            if (r0 < M) {
                float2 st;
                st.x = fmaxf(acc[mi][nj][0] + bv0, 0.f);
                st.y = fmaxf(acc[mi][nj][1] + bv1, 0.f);
                *(float2*)(C + (size_t)r0 * Nc + col) = st;
            }
            if (r0 + 8 < M) {
                float2 st;
                st.x = fmaxf(acc[mi][nj][2] + bv0, 0.f);
                st.y = fmaxf(acc[mi][nj][3] + bv1, 0.f);
                *(float2*)(C + (size_t)(r0 + 8) * Nc + col) = st;
            }
        }
    }
}

// ---------------- host launch: kernel launches ONLY ----------------
extern "C" void kernel_launch(void* const* d_in, const int* in_sizes, int n_in,
                              void* d_out, int out_size)
{
    // ---- size-based input binding (robust to metadata ordering) ----
    const float* x  = nullptr;  const int* ei = nullptr;
    const float* W1 = nullptr;  const float* W2 = nullptr; const float* Wp = nullptr;
    const float* b1 = nullptr;  const float* b2 = nullptr; const float* bp = nullptr;
    {
        int nw = 0, nb = 0;
        const float* wbig[2] = {nullptr, nullptr};
        const float* bias[3] = {nullptr, nullptr, nullptr};
        const float* xcand = nullptr; const int* eicand = nullptr;
        const float* w2cand = nullptr;
        for (int i = 0; i < n_in; i++) {
            int sz = in_sizes[i];
            if (sz >= 4000000)                      xcand  = (const float*)d_in[i];
            else if (sz >= 1000000)                 eicand = (const int*)d_in[i];
            else if (sz == 65536)                   w2cand = (const float*)d_in[i];
            else if (sz == 32768 && nw < 2)         wbig[nw++] = (const float*)d_in[i];
            else if (sz == 256 && nb < 3)           bias[nb++] = (const float*)d_in[i];
        }
        x = xcand; ei = eicand; W2 = w2cand;
        W1 = wbig[0]; Wp = wbig[1];
        b1 = bias[0]; b2 = bias[1]; bp = bias[2];
        if (!x || !ei || !W1 || !W2 || !Wp || !b1 || !b2 || !bp) {
            x  = (const float*)d_in[0]; ei = (const int*)d_in[1];
            W1 = (const float*)d_in[2]; b1 = (const float*)d_in[3];
            W2 = (const float*)d_in[4]; b2 = (const float*)d_in[5];
            Wp = (const float*)d_in[6]; bp = (const float*)d_in[7];
        }
    }
    float* out = (float*)d_out;

    int N_ = out_size / 256;                 if (N_ > MAXN) N_ = MAXN;
    int E_ = 0;
    for (int i = 0; i < n_in; i++)
        if ((const int*)d_in[i] == ei) { E_ = in_sizes[i] / 2; break; }
    if (E_ > MAXE) E_ = MAXE;

    int tb = 256;
    int nbN = (N_ + tb - 1) / tb;
    int nbE = (E_ + tb - 1) / tb;
    int nScan = (N_ + 1023) / 1024;

    // CSR build (edge_index as int32, all indices bounds-guarded)
    zero_cnt_kernel<<<nbN, tb>>>(N_);
    count_kernel<<<nbE, tb>>>(ei, E_, N_);
    scan_block_kernel<<<nScan, 1024>>>(N_);
    scan_partials_kernel<<<1, 32>>>(nScan);
    scan_add_kernel<<<nbN, tb>>>(N_);
    fill_kernel<<<nbE, tb>>>(ei, E_, N_);

    int aggBlocks = (N_ * 32 + tb - 1) / tb;
    dim3 gGrid(2, (N_ + 127) / 128);   // 256 cols / 128

    // A1 = Agg(x) -> g_S
    agg_x_kernel<<<aggBlocks, tb>>>(x, N_);
    // H = relu(A1 @ W1 + b1) -> d_out (scratch)
    gemm_tf32_kernel<<<gGrid, tb>>>(W1, 128, nullptr, nullptr, 0, b1, nullptr, out, N_);
    // A2 = Agg(H) -> g_S
    agg_h_kernel<<<aggBlocks, tb>>>(out, N_);
    // out = relu(A2 @ W2 + x @ Wp + b2 + bp)
    gemm_tf32_kernel<<<gGrid, tb>>>(W2, 256, x, Wp, 128, b2, bp, out, N_);
}